// round 15
// baseline (speedup 1.0000x reference)
#include <cuda_runtime.h>
#include <cuda_bf16.h>
#include <math_constants.h>
#include <cstdint>

#define BB 4
#define CC 64
#define NN 8192
#define OO 128
#define KK 20
#define BN (BB*NN)

// ---------------- scratch (static device globals; no allocation) ----------------
__device__ float g_pd[268435456ull];              // [B*N, N] 2*dot - xx_m   (1 GB)
__device__ float g_xt[(size_t)BN*CC];             // x transposed: [B*N, C]
__device__ float g_xx[BN];                        // squared norms
__device__ float g_pt[(size_t)BN*256];            // per point: P[128] then T[128]
__device__ int   g_idx[(size_t)BN*KK];            // top-20 neighbor indices
__device__ __nv_bfloat16 g_xs[(size_t)BN*128];    // per point: hi[64] then lo[64]
__device__ int   g_dummy[32];

__global__ void k_nop(int tag) {
    if (threadIdx.x == 0 && blockIdx.x == 0) g_dummy[tag] = tag;
}

// ---------------- K0: transpose x + squared norms + bf16 hi/lo split ----------------
__global__ __launch_bounds__(256) void k_split(const float* __restrict__ x) {
    int g = blockIdx.x * 256 + threadIdx.x;
    int b = g >> 13, n = g & (NN - 1);
    const float* xb = x + (size_t)b * CC * NN + n;
    float a0 = 0.f, a1 = 0.f, a2 = 0.f, a3 = 0.f;
#pragma unroll
    for (int c = 0; c < CC; c += 4) {
        float v0 = xb[(size_t)c * NN];
        float v1 = xb[(size_t)(c + 1) * NN];
        float v2 = xb[(size_t)(c + 2) * NN];
        float v3 = xb[(size_t)(c + 3) * NN];
        a0 = fmaf(v0, v0, a0); a1 = fmaf(v1, v1, a1);
        a2 = fmaf(v2, v2, a2); a3 = fmaf(v3, v3, a3);
        g_xt[(size_t)g * CC + c]     = v0;
        g_xt[(size_t)g * CC + c + 1] = v1;
        g_xt[(size_t)g * CC + c + 2] = v2;
        g_xt[(size_t)g * CC + c + 3] = v3;
        float vv[4] = {v0, v1, v2, v3};
#pragma unroll
        for (int j = 0; j < 4; j++) {
            __nv_bfloat16 hi = __float2bfloat16(vv[j]);
            __nv_bfloat16 lo = __float2bfloat16(vv[j] - __bfloat162float(hi));
            g_xs[(size_t)g * 128 + c + j]      = hi;
            g_xs[(size_t)g * 128 + 64 + c + j] = lo;
        }
    }
    g_xx[g] = (a0 + a1) + (a2 + a3);
}

// ---------------- K1: distance GEMM via HMMA, writes pd (no fusion) ----------------
// 256 threads (8 warps). Block computes a 128x128 pd tile: rows n0.., cols m0..
// Warp w owns rows [w*16,(w+1)*16). pd[row][col] = 2*dot - xx_m  (row-const -xx_n
// dropped: doesn't change per-row ordering).
// smem: As [0,34816) Bs [34816,69632) xxm [69632,70144)
static constexpr int AS_OFF   = 0;
static constexpr int BS_OFF   = 34816;
static constexpr int XXM_OFF  = 69632;
static constexpr int SM_DIST  = 70144;

__device__ __forceinline__ void mma16816(float* d, const uint32_t* a,
                                         uint32_t b0, uint32_t b1) {
    asm volatile(
        "mma.sync.aligned.m16n8k16.row.col.f32.bf16.bf16.f32 "
        "{%0,%1,%2,%3}, {%4,%5,%6,%7}, {%8,%9}, {%0,%1,%2,%3};"
        : "+f"(d[0]), "+f"(d[1]), "+f"(d[2]), "+f"(d[3])
        : "r"(a[0]), "r"(a[1]), "r"(a[2]), "r"(a[3]), "r"(b0), "r"(b1));
}

__global__ __launch_bounds__(256) void k_dist() {
    extern __shared__ char smem[];
    char*  smAs = smem + AS_OFF;
    char*  smBs = smem + BS_OFF;
    float* xxm  = (float*)(smem + XXM_OFF);

    int t = threadIdx.x, lane = t & 31, wid = t >> 5;
    int b = blockIdx.z;
    int n0 = blockIdx.y << 7, m0 = blockIdx.x << 7;

    // load A tile (rows n0..) and B tile (cols m0..): 2 x 128 pts x 256B
    {
        const uint4* srcA = (const uint4*)(g_xs + (size_t)(b * NN + n0) * 128);
        const uint4* srcB = (const uint4*)(g_xs + (size_t)(b * NN + m0) * 128);
#pragma unroll
        for (int i = t; i < 4096; i += 256) {
            int tile = i >> 11, j = i & 2047;
            int p = j >> 4, s = j & 15;
            uint4 v = tile ? srcB[j] : srcA[j];
            *(uint4*)((tile ? smBs : smAs) + p * 272 + s * 16) = v;
        }
        if (t < 128) xxm[t] = g_xx[b * NN + m0 + t];
    }
    __syncthreads();

    // A fragments for this warp's 16 rows (from smem)
    uint32_t afr[2][4][4];
    {
        int r = wid * 16 + (lane >> 2);
#pragma unroll
        for (int h = 0; h < 2; h++)
#pragma unroll
            for (int ks = 0; ks < 4; ks++) {
                int bk = h * 64 + ks * 16 + (lane & 3) * 2;
                const char* pa = smAs + r * 272 + bk * 2;
                afr[h][ks][0] = *(const uint32_t*)pa;
                afr[h][ks][1] = *(const uint32_t*)(pa + 8 * 272);
                afr[h][ks][2] = *(const uint32_t*)(pa + 16);
                afr[h][ks][3] = *(const uint32_t*)(pa + 8 * 272 + 16);
            }
    }

    // accumulate full 128-column strip: d[16][4]
    float d[16][4];
#pragma unroll
    for (int nt = 0; nt < 16; nt++)
#pragma unroll
        for (int q = 0; q < 4; q++) d[nt][q] = 0.f;

#pragma unroll
    for (int pass = 0; pass < 3; pass++) {
        const int Ap = (pass == 2) ? 1 : 0;
        const int Bp = (pass == 1) ? 1 : 0;
#pragma unroll
        for (int ks = 0; ks < 4; ks++) {
            int kb = Bp * 64 + ks * 16 + (lane & 3) * 2;
#pragma unroll
            for (int nt = 0; nt < 16; nt++) {
                int n = nt * 8 + (lane >> 2);
                uint32_t b0 = *(const uint32_t*)(smBs + n * 272 + kb * 2);
                uint32_t b1 = *(const uint32_t*)(smBs + n * 272 + kb * 2 + 16);
                mma16816(d[nt], afr[Ap][ks], b0, b1);
            }
        }
    }

    // epilogue: pd[row][col] = 2*dot - xxm[col]   (float2 stores)
    {
        int r = wid * 16 + (lane >> 2);
        size_t row0 = (size_t)(b * NN + n0 + r) * NN + m0;
        size_t row8 = row0 + (size_t)8 * NN;
#pragma unroll
        for (int nt = 0; nt < 16; nt++) {
            int cj = nt * 8 + (lane & 3) * 2;
            float xm0 = xxm[cj], xm1 = xxm[cj + 1];
            float2 lo = make_float2(2.f * d[nt][0] - xm0, 2.f * d[nt][1] - xm1);
            float2 hi = make_float2(2.f * d[nt][2] - xm0, 2.f * d[nt][3] - xm1);
            *(float2*)&g_pd[row0 + cj] = lo;
            *(float2*)&g_pd[row8 + cj] = hi;
        }
    }
}

// ---------------- K2: top-20 per row (R1-proven code; set semantics) ----------------
__global__ __launch_bounds__(256) void k_topk() {
    __shared__ float sv[256 * KK];
    __shared__ int   si[256 * KK];
    __shared__ float wv[8 * KK];
    __shared__ int   wi[8 * KK];
    int g = blockIdx.x;
    const float* row = g_pd + (size_t)g * NN;
    int t = threadIdx.x;

    float lv[KK]; int li[KK];
#pragma unroll
    for (int j = 0; j < KK; j++) { int m = t + j * 256; lv[j] = row[m]; li[j] = m; }
    float mn = CUDART_INF_F; int mp = 0;
#pragma unroll
    for (int j = 0; j < KK; j++) if (lv[j] < mn) { mn = lv[j]; mp = j; }
    for (int j = KK; j < 32; j++) {
        int m = t + j * 256; float v = row[m];
        if (v > mn) {
            lv[mp] = v; li[mp] = m;
            mn = CUDART_INF_F;
            for (int jj = 0; jj < KK; jj++) if (lv[jj] < mn) { mn = lv[jj]; mp = jj; }
        }
    }
    for (int i = 1; i < KK; i++) {
        float v = lv[i]; int id = li[i]; int j = i - 1;
        while (j >= 0 && lv[j] < v) { lv[j + 1] = lv[j]; li[j + 1] = li[j]; j--; }
        lv[j + 1] = v; li[j + 1] = id;
    }
    for (int j = 0; j < KK; j++) { sv[t * KK + j] = lv[j]; si[t * KK + j] = li[j]; }
    __syncthreads();

    int lane = t & 31, w = t >> 5;
    {
        int h = 0; float myv = sv[t * KK];
        for (int r = 0; r < KK; r++) {
            float v = myv; int src = lane;
#pragma unroll
            for (int off = 16; off > 0; off >>= 1) {
                float ov = __shfl_xor_sync(0xffffffffu, v, off);
                int   os = __shfl_xor_sync(0xffffffffu, src, off);
                if (ov > v || (ov == v && os < src)) { v = ov; src = os; }
            }
            if (lane == src) {
                wv[w * KK + r] = v; wi[w * KK + r] = si[t * KK + h];
                h++;
                myv = (h < KK) ? sv[t * KK + h] : -CUDART_INF_F;
            }
        }
    }
    __syncthreads();
    if (w == 0) {
        int h = 0;
        float myv = (lane < 8) ? wv[lane * KK] : -CUDART_INF_F;
        for (int r = 0; r < KK; r++) {
            float v = myv; int src = lane;
#pragma unroll
            for (int off = 16; off > 0; off >>= 1) {
                float ov = __shfl_xor_sync(0xffffffffu, v, off);
                int   os = __shfl_xor_sync(0xffffffffu, src, off);
                if (ov > v || (ov == v && os < src)) { v = ov; src = os; }
            }
            if (lane == src) {
                g_idx[(size_t)g * KK + r] = wi[lane * KK + h];
                h++;
                myv = (h < KK && lane < 8) ? wv[lane * KK + h] : -CUDART_INF_F;
            }
        }
    }
}

// ---------------- K3: P = W1a·x_n ; T = (W1b - W1a)·x_n  (ILP-4 accumulators) ----------------
__global__ __launch_bounds__(128) void k_pt(const float* __restrict__ W1) {
    extern __shared__ float sm[];
    float* Wt = sm;
    __shared__ float xr[64];
    int t = threadIdx.x;
    for (int s = t; s < 128 * 128; s += 128) {
        int d = s >> 7, c = s & 127;
        float wvv = W1[d * 128 + c];
        if (c >= 64) wvv -= W1[d * 128 + c - 64];
        Wt[c * 129 + d] = wvv;
    }
    __syncthreads();
    int g0 = blockIdx.x * 32;
    for (int nn = 0; nn < 32; nn++) {
        int g = g0 + nn;
        if (t < 64) xr[t] = g_xt[(size_t)g * CC + t];
        __syncthreads();
        float p0 = 0.f, p1 = 0.f, p2 = 0.f, p3 = 0.f;
        float t0 = 0.f, t1 = 0.f, t2 = 0.f, t3 = 0.f;
#pragma unroll
        for (int c = 0; c < 64; c += 4) {
            float x0 = xr[c], x1 = xr[c + 1], x2 = xr[c + 2], x3 = xr[c + 3];
            p0 = fmaf(Wt[c * 129 + t],       x0, p0);
            p1 = fmaf(Wt[(c + 1) * 129 + t], x1, p1);
            p2 = fmaf(Wt[(c + 2) * 129 + t], x2, p2);
            p3 = fmaf(Wt[(c + 3) * 129 + t], x3, p3);
            t0 = fmaf(Wt[(c + 64) * 129 + t], x0, t0);
            t1 = fmaf(Wt[(c + 65) * 129 + t], x1, t1);
            t2 = fmaf(Wt[(c + 66) * 129 + t], x2, t2);
            t3 = fmaf(Wt[(c + 67) * 129 + t], x3, t3);
        }
        g_pt[(size_t)g * 256 + t]       = (p0 + p1) + (p2 + p3);
        g_pt[(size_t)g * 256 + 128 + t] = (t0 + t1) + (t2 + t3);
        __syncthreads();
    }
}

// ---------------- K4: gather + softmax_k + g-collapse + W2 matvec (ILP-4) ----------------
__global__ __launch_bounds__(128) void k_out(const float* __restrict__ W2,
                                             float* __restrict__ out) {
    extern __shared__ float sm[];
    float* W2t = sm;
    __shared__ float gs[128];
    __shared__ float ctrs[64];
    __shared__ int   nid[KK];
    int t = threadIdx.x;
    for (int s = t; s < 128 * 128; s += 128) {
        int o = s >> 7, c = s & 127;
        W2t[c * 129 + o] = W2[o * 128 + c];
    }
    __syncthreads();
    int g0 = blockIdx.x * 16;
    for (int nn = 0; nn < 16; nn++) {
        int g = g0 + nn;
        int b = g >> 13, n = g & (NN - 1);
        if (t < KK) nid[t] = g_idx[(size_t)g * KK + t];
        if (t < 64) ctrs[t] = g_xt[(size_t)g * CC + t];
        float tvv = g_pt[(size_t)g * 256 + 128 + t];
        __syncthreads();

        float h[KK];
#pragma unroll
        for (int k = 0; k < KK; k++) {
            int ng = (b << 13) + nid[k];
            h[k] = g_pt[(size_t)ng * 256 + t] + tvv;
        }
        float hm = -CUDART_INF_F;
#pragma unroll
        for (int k = 0; k < KK; k++) hm = fmaxf(hm, h[k]);
        float s = 0.f;
#pragma unroll
        for (int k = 0; k < KK; k++) { float e = __expf(h[k] - hm); s += e; h[k] = e; }
        float inv = 1.f / s;

        float gd;
        if (t < 64) {
            float c0 = ctrs[t];
            float a0 = 0.f, a1 = 0.f, a2 = 0.f, a3 = 0.f;
#pragma unroll
            for (int k = 0; k < KK; k += 4) {
                a0 = fmaf(g_xt[(size_t)((b << 13) + nid[k])     * CC + t] - c0, h[k],     a0);
                a1 = fmaf(g_xt[(size_t)((b << 13) + nid[k + 1]) * CC + t] - c0, h[k + 1], a1);
                a2 = fmaf(g_xt[(size_t)((b << 13) + nid[k + 2]) * CC + t] - c0, h[k + 2], a2);
                a3 = fmaf(g_xt[(size_t)((b << 13) + nid[k + 3]) * CC + t] - c0, h[k + 3], a3);
            }
            gd = ((a0 + a1) + (a2 + a3)) * inv;
        } else {
            float s0 = 0.f, s1 = 0.f, s2 = 0.f, s3 = 0.f;
#pragma unroll
            for (int k = 0; k < KK; k += 4) {
                s0 += h[k]; s1 += h[k + 1]; s2 += h[k + 2]; s3 += h[k + 3];
            }
            gd = ctrs[t - 64] * ((s0 + s1) + (s2 + s3)) * inv;
        }
        gs[t] = gd;
        __syncthreads();

        float c0 = 0.f, c1 = 0.f, c2 = 0.f, c3 = 0.f;
#pragma unroll
        for (int c = 0; c < 128; c += 4) {
            c0 = fmaf(W2t[c * 129 + t],       gs[c],     c0);
            c1 = fmaf(W2t[(c + 1) * 129 + t], gs[c + 1], c1);
            c2 = fmaf(W2t[(c + 2) * 129 + t], gs[c + 2], c2);
            c3 = fmaf(W2t[(c + 3) * 129 + t], gs[c + 3], c3);
        }
        out[((size_t)b * OO + t) * NN + n] = (c0 + c1) + (c2 + c3);
        __syncthreads();
    }
}

// ---------------- launch ----------------
extern "C" void kernel_launch(void* const* d_in, const int* in_sizes, int n_in,
                              void* d_out, int out_size) {
    const float* x  = (const float*)d_in[0];
    const float* W1 = (const float*)d_in[1];
    const float* W2 = (const float*)d_in[2];
    float* out = (float*)d_out;

    cudaFuncSetAttribute(k_dist, cudaFuncAttributeMaxDynamicSharedMemorySize, SM_DIST);
    cudaFuncSetAttribute(k_pt,   cudaFuncAttributeMaxDynamicSharedMemorySize, 128 * 129 * 4);
    cudaFuncSetAttribute(k_out,  cudaFuncAttributeMaxDynamicSharedMemorySize, 128 * 129 * 4);

    k_split<<<BN / 256, 256>>>(x);
    k_nop<<<1, 32>>>(1);                 // keep k_dist in ncu's profiled slot (4th)
    k_nop<<<1, 32>>>(2);
    k_dist<<<dim3(64, 64, 4), 256, SM_DIST>>>();
    k_topk<<<BN, 256>>>();
    k_pt<<<BN / 32, 128, 128 * 129 * 4>>>(W1);
    k_out<<<BN / 16, 128, 128 * 129 * 4>>>(W2, out);
}

// round 16
// speedup vs baseline: 1.4652x; 1.4652x over previous
#include <cuda_runtime.h>
#include <cuda_bf16.h>
#include <math_constants.h>
#include <cstdint>

#define BB 4
#define CC 64
#define NN 8192
#define OO 128
#define KK 20
#define BN (BB*NN)

// ---------------- scratch (static device globals; no allocation) ----------------
__device__ float g_pd[268435456ull];              // [B*N, N] 2*dot - xx_m   (1 GB)
__device__ float g_xt[(size_t)BN*CC];             // x transposed: [B*N, C]
__device__ float g_xx[BN];                        // squared norms
__device__ float g_pt[(size_t)BN*256];            // per point: P[128] then T[128]
__device__ int   g_idx[(size_t)BN*KK];            // top-20 neighbor indices
__device__ __nv_bfloat16 g_xs[(size_t)BN*128];    // per point: hi[64] then lo[64]
__device__ int   g_dummy[32];

__global__ void k_nop(int tag) {
    if (threadIdx.x == 0 && blockIdx.x == 0) g_dummy[tag] = tag;
}

// ---------------- K0: transpose x + squared norms + bf16 hi/lo split ----------------
__global__ __launch_bounds__(256) void k_split(const float* __restrict__ x) {
    int g = blockIdx.x * 256 + threadIdx.x;
    int b = g >> 13, n = g & (NN - 1);
    const float* xb = x + (size_t)b * CC * NN + n;
    float a0 = 0.f, a1 = 0.f, a2 = 0.f, a3 = 0.f;
#pragma unroll
    for (int c = 0; c < CC; c += 4) {
        float v0 = xb[(size_t)c * NN];
        float v1 = xb[(size_t)(c + 1) * NN];
        float v2 = xb[(size_t)(c + 2) * NN];
        float v3 = xb[(size_t)(c + 3) * NN];
        a0 = fmaf(v0, v0, a0); a1 = fmaf(v1, v1, a1);
        a2 = fmaf(v2, v2, a2); a3 = fmaf(v3, v3, a3);
        g_xt[(size_t)g * CC + c]     = v0;
        g_xt[(size_t)g * CC + c + 1] = v1;
        g_xt[(size_t)g * CC + c + 2] = v2;
        g_xt[(size_t)g * CC + c + 3] = v3;
        float vv[4] = {v0, v1, v2, v3};
#pragma unroll
        for (int j = 0; j < 4; j++) {
            __nv_bfloat16 hi = __float2bfloat16(vv[j]);
            __nv_bfloat16 lo = __float2bfloat16(vv[j] - __bfloat162float(hi));
            g_xs[(size_t)g * 128 + c + j]      = hi;
            g_xs[(size_t)g * 128 + 64 + c + j] = lo;
        }
    }
    g_xx[g] = (a0 + a1) + (a2 + a3);
}

// ---------------- K1: distance GEMM via HMMA, writes pd (measured 389us) ----------------
static constexpr int AS_OFF   = 0;
static constexpr int BS_OFF   = 34816;
static constexpr int XXM_OFF  = 69632;
static constexpr int SM_DIST  = 70144;

__device__ __forceinline__ void mma16816(float* d, const uint32_t* a,
                                         uint32_t b0, uint32_t b1) {
    asm volatile(
        "mma.sync.aligned.m16n8k16.row.col.f32.bf16.bf16.f32 "
        "{%0,%1,%2,%3}, {%4,%5,%6,%7}, {%8,%9}, {%0,%1,%2,%3};"
        : "+f"(d[0]), "+f"(d[1]), "+f"(d[2]), "+f"(d[3])
        : "r"(a[0]), "r"(a[1]), "r"(a[2]), "r"(a[3]), "r"(b0), "r"(b1));
}

__global__ __launch_bounds__(256) void k_dist() {
    extern __shared__ char smem[];
    char*  smAs = smem + AS_OFF;
    char*  smBs = smem + BS_OFF;
    float* xxm  = (float*)(smem + XXM_OFF);

    int t = threadIdx.x, lane = t & 31, wid = t >> 5;
    int b = blockIdx.z;
    int n0 = blockIdx.y << 7, m0 = blockIdx.x << 7;

    {
        const uint4* srcA = (const uint4*)(g_xs + (size_t)(b * NN + n0) * 128);
        const uint4* srcB = (const uint4*)(g_xs + (size_t)(b * NN + m0) * 128);
#pragma unroll
        for (int i = t; i < 4096; i += 256) {
            int tile = i >> 11, j = i & 2047;
            int p = j >> 4, s = j & 15;
            uint4 v = tile ? srcB[j] : srcA[j];
            *(uint4*)((tile ? smBs : smAs) + p * 272 + s * 16) = v;
        }
        if (t < 128) xxm[t] = g_xx[b * NN + m0 + t];
    }
    __syncthreads();

    uint32_t afr[2][4][4];
    {
        int r = wid * 16 + (lane >> 2);
#pragma unroll
        for (int h = 0; h < 2; h++)
#pragma unroll
            for (int ks = 0; ks < 4; ks++) {
                int bk = h * 64 + ks * 16 + (lane & 3) * 2;
                const char* pa = smAs + r * 272 + bk * 2;
                afr[h][ks][0] = *(const uint32_t*)pa;
                afr[h][ks][1] = *(const uint32_t*)(pa + 8 * 272);
                afr[h][ks][2] = *(const uint32_t*)(pa + 16);
                afr[h][ks][3] = *(const uint32_t*)(pa + 8 * 272 + 16);
            }
    }

    float d[16][4];
#pragma unroll
    for (int nt = 0; nt < 16; nt++)
#pragma unroll
        for (int q = 0; q < 4; q++) d[nt][q] = 0.f;

#pragma unroll
    for (int pass = 0; pass < 3; pass++) {
        const int Ap = (pass == 2) ? 1 : 0;
        const int Bp = (pass == 1) ? 1 : 0;
#pragma unroll
        for (int ks = 0; ks < 4; ks++) {
            int kb = Bp * 64 + ks * 16 + (lane & 3) * 2;
#pragma unroll
            for (int nt = 0; nt < 16; nt++) {
                int n = nt * 8 + (lane >> 2);
                uint32_t b0 = *(const uint32_t*)(smBs + n * 272 + kb * 2);
                uint32_t b1 = *(const uint32_t*)(smBs + n * 272 + kb * 2 + 16);
                mma16816(d[nt], afr[Ap][ks], b0, b1);
            }
        }
    }

    {
        int r = wid * 16 + (lane >> 2);
        size_t row0 = (size_t)(b * NN + n0 + r) * NN + m0;
        size_t row8 = row0 + (size_t)8 * NN;
#pragma unroll
        for (int nt = 0; nt < 16; nt++) {
            int cj = nt * 8 + (lane & 3) * 2;
            float xm0 = xxm[cj], xm1 = xxm[cj + 1];
            float2 lo = make_float2(2.f * d[nt][0] - xm0, 2.f * d[nt][1] - xm1);
            float2 hi = make_float2(2.f * d[nt][2] - xm0, 2.f * d[nt][3] - xm1);
            *(float2*)&g_pd[row0 + cj] = lo;
            *(float2*)&g_pd[row8 + cj] = hi;
        }
    }
}

// ---------------- K2: top-20 per row — warp-per-row, register-resident ----------------
// 8 warps/block, each warp owns one row independently. No smem, no block syncs.
// Per lane: 256 coalesced candidates, predicated top-20 (thrpos trick).
// Merge: 20 rounds of cached local-max + shfl argmax; winner pops (predicated).
__global__ __launch_bounds__(256) void k_topk() {
    int t = threadIdx.x, lane = t & 31, w = t >> 5;
    int g = blockIdx.x * 8 + w;
    const float* row = g_pd + (size_t)g * NN;

    float tv[KK]; int ti[KK];
#pragma unroll
    for (int q = 0; q < KK; q++) { tv[q] = -CUDART_INF_F; ti[q] = 0; }
    float thr = -CUDART_INF_F; int thrpos = 0;

#pragma unroll 1
    for (int j = 0; j < 256; j += 4) {
        float v0 = row[j * 32 + lane];
        float v1 = row[(j + 1) * 32 + lane];
        float v2 = row[(j + 2) * 32 + lane];
        float v3 = row[(j + 3) * 32 + lane];
#pragma unroll
        for (int i = 0; i < 4; i++) {
            float v = (i == 0) ? v0 : (i == 1) ? v1 : (i == 2) ? v2 : v3;
            if (v > thr) {
                int col = (j + i) * 32 + lane;
#pragma unroll
                for (int q = 0; q < KK; q++)
                    if (q == thrpos) { tv[q] = v; ti[q] = col; }
                thr = tv[0]; thrpos = 0;
#pragma unroll
                for (int q = 1; q < KK; q++)
                    if (tv[q] < thr) { thr = tv[q]; thrpos = q; }
            }
        }
    }

    // cached local max
    float lmax = -CUDART_INF_F; int lpos = 0;
#pragma unroll
    for (int q = 0; q < KK; q++)
        if (tv[q] > lmax) { lmax = tv[q]; lpos = q; }

    // 20 rounds: warp argmax, winner emits + pops + recomputes local max
    for (int r = 0; r < KK; r++) {
        float v = lmax; int src = lane;
#pragma unroll
        for (int off = 16; off > 0; off >>= 1) {
            float ov = __shfl_xor_sync(0xffffffffu, v, off);
            int   os = __shfl_xor_sync(0xffffffffu, src, off);
            if (ov > v || (ov == v && os < src)) { v = ov; src = os; }
        }
        if (lane == src) {
            int outi = 0;
#pragma unroll
            for (int q = 0; q < KK; q++)
                if (q == lpos) outi = ti[q];
            g_idx[(size_t)g * KK + r] = outi;
#pragma unroll
            for (int q = 0; q < KK; q++)
                if (q == lpos) tv[q] = -CUDART_INF_F;
            lmax = -CUDART_INF_F; lpos = 0;
#pragma unroll
            for (int q = 0; q < KK; q++)
                if (tv[q] > lmax) { lmax = tv[q]; lpos = q; }
        }
        __syncwarp();
    }
}

// ---------------- K3: P = W1a·x_n ; T = (W1b - W1a)·x_n  (ILP-4 accumulators) ----------------
__global__ __launch_bounds__(128) void k_pt(const float* __restrict__ W1) {
    extern __shared__ float sm[];
    float* Wt = sm;
    __shared__ float xr[64];
    int t = threadIdx.x;
    for (int s = t; s < 128 * 128; s += 128) {
        int d = s >> 7, c = s & 127;
        float wvv = W1[d * 128 + c];
        if (c >= 64) wvv -= W1[d * 128 + c - 64];
        Wt[c * 129 + d] = wvv;
    }
    __syncthreads();
    int g0 = blockIdx.x * 32;
    for (int nn = 0; nn < 32; nn++) {
        int g = g0 + nn;
        if (t < 64) xr[t] = g_xt[(size_t)g * CC + t];
        __syncthreads();
        float p0 = 0.f, p1 = 0.f, p2 = 0.f, p3 = 0.f;
        float t0 = 0.f, t1 = 0.f, t2 = 0.f, t3 = 0.f;
#pragma unroll
        for (int c = 0; c < 64; c += 4) {
            float x0 = xr[c], x1 = xr[c + 1], x2 = xr[c + 2], x3 = xr[c + 3];
            p0 = fmaf(Wt[c * 129 + t],       x0, p0);
            p1 = fmaf(Wt[(c + 1) * 129 + t], x1, p1);
            p2 = fmaf(Wt[(c + 2) * 129 + t], x2, p2);
            p3 = fmaf(Wt[(c + 3) * 129 + t], x3, p3);
            t0 = fmaf(Wt[(c + 64) * 129 + t], x0, t0);
            t1 = fmaf(Wt[(c + 65) * 129 + t], x1, t1);
            t2 = fmaf(Wt[(c + 66) * 129 + t], x2, t2);
            t3 = fmaf(Wt[(c + 67) * 129 + t], x3, t3);
        }
        g_pt[(size_t)g * 256 + t]       = (p0 + p1) + (p2 + p3);
        g_pt[(size_t)g * 256 + 128 + t] = (t0 + t1) + (t2 + t3);
        __syncthreads();
    }
}

// ---------------- K4: gather + softmax_k + g-collapse + W2 matvec (ILP-4) ----------------
__global__ __launch_bounds__(128) void k_out(const float* __restrict__ W2,
                                             float* __restrict__ out) {
    extern __shared__ float sm[];
    float* W2t = sm;
    __shared__ float gs[128];
    __shared__ float ctrs[64];
    __shared__ int   nid[KK];
    int t = threadIdx.x;
    for (int s = t; s < 128 * 128; s += 128) {
        int o = s >> 7, c = s & 127;
        W2t[c * 129 + o] = W2[o * 128 + c];
    }
    __syncthreads();
    int g0 = blockIdx.x * 16;
    for (int nn = 0; nn < 16; nn++) {
        int g = g0 + nn;
        int b = g >> 13, n = g & (NN - 1);
        if (t < KK) nid[t] = g_idx[(size_t)g * KK + t];
        if (t < 64) ctrs[t] = g_xt[(size_t)g * CC + t];
        float tvv = g_pt[(size_t)g * 256 + 128 + t];
        __syncthreads();

        float h[KK];
#pragma unroll
        for (int k = 0; k < KK; k++) {
            int ng = (b << 13) + nid[k];
            h[k] = g_pt[(size_t)ng * 256 + t] + tvv;
        }
        float hm = -CUDART_INF_F;
#pragma unroll
        for (int k = 0; k < KK; k++) hm = fmaxf(hm, h[k]);
        float s = 0.f;
#pragma unroll
        for (int k = 0; k < KK; k++) { float e = __expf(h[k] - hm); s += e; h[k] = e; }
        float inv = 1.f / s;

        float gd;
        if (t < 64) {
            float c0 = ctrs[t];
            float a0 = 0.f, a1 = 0.f, a2 = 0.f, a3 = 0.f;
#pragma unroll
            for (int k = 0; k < KK; k += 4) {
                a0 = fmaf(g_xt[(size_t)((b << 13) + nid[k])     * CC + t] - c0, h[k],     a0);
                a1 = fmaf(g_xt[(size_t)((b << 13) + nid[k + 1]) * CC + t] - c0, h[k + 1], a1);
                a2 = fmaf(g_xt[(size_t)((b << 13) + nid[k + 2]) * CC + t] - c0, h[k + 2], a2);
                a3 = fmaf(g_xt[(size_t)((b << 13) + nid[k + 3]) * CC + t] - c0, h[k + 3], a3);
            }
            gd = ((a0 + a1) + (a2 + a3)) * inv;
        } else {
            float s0 = 0.f, s1 = 0.f, s2 = 0.f, s3 = 0.f;
#pragma unroll
            for (int k = 0; k < KK; k += 4) {
                s0 += h[k]; s1 += h[k + 1]; s2 += h[k + 2]; s3 += h[k + 3];
            }
            gd = ctrs[t - 64] * ((s0 + s1) + (s2 + s3)) * inv;
        }
        gs[t] = gd;
        __syncthreads();

        float c0 = 0.f, c1 = 0.f, c2 = 0.f, c3 = 0.f;
#pragma unroll
        for (int c = 0; c < 128; c += 4) {
            c0 = fmaf(W2t[c * 129 + t],       gs[c],     c0);
            c1 = fmaf(W2t[(c + 1) * 129 + t], gs[c + 1], c1);
            c2 = fmaf(W2t[(c + 2) * 129 + t], gs[c + 2], c2);
            c3 = fmaf(W2t[(c + 3) * 129 + t], gs[c + 3], c3);
        }
        out[((size_t)b * OO + t) * NN + n] = (c0 + c1) + (c2 + c3);
        __syncthreads();
    }
}

// ---------------- launch ----------------
extern "C" void kernel_launch(void* const* d_in, const int* in_sizes, int n_in,
                              void* d_out, int out_size) {
    const float* x  = (const float*)d_in[0];
    const float* W1 = (const float*)d_in[1];
    const float* W2 = (const float*)d_in[2];
    float* out = (float*)d_out;

    cudaFuncSetAttribute(k_dist, cudaFuncAttributeMaxDynamicSharedMemorySize, SM_DIST);
    cudaFuncSetAttribute(k_pt,   cudaFuncAttributeMaxDynamicSharedMemorySize, 128 * 129 * 4);
    cudaFuncSetAttribute(k_out,  cudaFuncAttributeMaxDynamicSharedMemorySize, 128 * 129 * 4);

    k_split<<<BN / 256, 256>>>(x);
    k_nop<<<1, 32>>>(1);                 // k_topk lands in ncu's profiled 4th slot
    k_dist<<<dim3(64, 64, 4), 256, SM_DIST>>>();
    k_topk<<<BN / 8, 256>>>();
    k_pt<<<BN / 32, 128, 128 * 129 * 4>>>(W1);
    k_out<<<BN / 16, 128, 128 * 129 * 4>>>(W2, out);
}

// round 17
// speedup vs baseline: 3.2517x; 2.2192x over previous
#include <cuda_runtime.h>
#include <cuda_bf16.h>
#include <math_constants.h>
#include <cstdint>

#define BB 4
#define CC 64
#define NN 8192
#define OO 128
#define KK 20
#define BN (BB*NN)

// ---------------- scratch (static device globals; no allocation) ----------------
__device__ float g_pd[268435456ull];              // [B*N, N] 2*dot - xx_m   (1 GB)
__device__ float g_xt[(size_t)BN*CC];             // x transposed: [B*N, C]
__device__ float g_xx[BN];                        // squared norms
__device__ float g_pt[(size_t)BN*256];            // per point: P[128] then T[128]
__device__ int   g_idx[(size_t)BN*KK];            // top-20 neighbor indices
__device__ __nv_bfloat16 g_xs[(size_t)BN*128];    // per point: hi[64] then lo[64]
__device__ int   g_dummy[32];

__global__ void k_nop(int tag) {
    if (threadIdx.x == 0 && blockIdx.x == 0) g_dummy[tag] = tag;
}

// ---------------- K0: transpose x + squared norms + bf16 hi/lo split ----------------
__global__ __launch_bounds__(256) void k_split(const float* __restrict__ x) {
    int g = blockIdx.x * 256 + threadIdx.x;
    int b = g >> 13, n = g & (NN - 1);
    const float* xb = x + (size_t)b * CC * NN + n;
    float a0 = 0.f, a1 = 0.f, a2 = 0.f, a3 = 0.f;
#pragma unroll
    for (int c = 0; c < CC; c += 4) {
        float v0 = xb[(size_t)c * NN];
        float v1 = xb[(size_t)(c + 1) * NN];
        float v2 = xb[(size_t)(c + 2) * NN];
        float v3 = xb[(size_t)(c + 3) * NN];
        a0 = fmaf(v0, v0, a0); a1 = fmaf(v1, v1, a1);
        a2 = fmaf(v2, v2, a2); a3 = fmaf(v3, v3, a3);
        g_xt[(size_t)g * CC + c]     = v0;
        g_xt[(size_t)g * CC + c + 1] = v1;
        g_xt[(size_t)g * CC + c + 2] = v2;
        g_xt[(size_t)g * CC + c + 3] = v3;
        float vv[4] = {v0, v1, v2, v3};
#pragma unroll
        for (int j = 0; j < 4; j++) {
            __nv_bfloat16 hi = __float2bfloat16(vv[j]);
            __nv_bfloat16 lo = __float2bfloat16(vv[j] - __bfloat162float(hi));
            g_xs[(size_t)g * 128 + c + j]      = hi;
            g_xs[(size_t)g * 128 + 64 + c + j] = lo;
        }
    }
    g_xx[g] = (a0 + a1) + (a2 + a3);
}

// ---------------- K1: distance GEMM via HMMA, writes pd (measured 389us) ----------------
static constexpr int AS_OFF   = 0;
static constexpr int BS_OFF   = 34816;
static constexpr int XXM_OFF  = 69632;
static constexpr int SM_DIST  = 70144;

__device__ __forceinline__ void mma16816(float* d, const uint32_t* a,
                                         uint32_t b0, uint32_t b1) {
    asm volatile(
        "mma.sync.aligned.m16n8k16.row.col.f32.bf16.bf16.f32 "
        "{%0,%1,%2,%3}, {%4,%5,%6,%7}, {%8,%9}, {%0,%1,%2,%3};"
        : "+f"(d[0]), "+f"(d[1]), "+f"(d[2]), "+f"(d[3])
        : "r"(a[0]), "r"(a[1]), "r"(a[2]), "r"(a[3]), "r"(b0), "r"(b1));
}

__global__ __launch_bounds__(256) void k_dist() {
    extern __shared__ char smem[];
    char*  smAs = smem + AS_OFF;
    char*  smBs = smem + BS_OFF;
    float* xxm  = (float*)(smem + XXM_OFF);

    int t = threadIdx.x, lane = t & 31, wid = t >> 5;
    int b = blockIdx.z;
    int n0 = blockIdx.y << 7, m0 = blockIdx.x << 7;

    {
        const uint4* srcA = (const uint4*)(g_xs + (size_t)(b * NN + n0) * 128);
        const uint4* srcB = (const uint4*)(g_xs + (size_t)(b * NN + m0) * 128);
#pragma unroll
        for (int i = t; i < 4096; i += 256) {
            int tile = i >> 11, j = i & 2047;
            int p = j >> 4, s = j & 15;
            uint4 v = tile ? srcB[j] : srcA[j];
            *(uint4*)((tile ? smBs : smAs) + p * 272 + s * 16) = v;
        }
        if (t < 128) xxm[t] = g_xx[b * NN + m0 + t];
    }
    __syncthreads();

    uint32_t afr[2][4][4];
    {
        int r = wid * 16 + (lane >> 2);
#pragma unroll
        for (int h = 0; h < 2; h++)
#pragma unroll
            for (int ks = 0; ks < 4; ks++) {
                int bk = h * 64 + ks * 16 + (lane & 3) * 2;
                const char* pa = smAs + r * 272 + bk * 2;
                afr[h][ks][0] = *(const uint32_t*)pa;
                afr[h][ks][1] = *(const uint32_t*)(pa + 8 * 272);
                afr[h][ks][2] = *(const uint32_t*)(pa + 16);
                afr[h][ks][3] = *(const uint32_t*)(pa + 8 * 272 + 16);
            }
    }

    float d[16][4];
#pragma unroll
    for (int nt = 0; nt < 16; nt++)
#pragma unroll
        for (int q = 0; q < 4; q++) d[nt][q] = 0.f;

#pragma unroll
    for (int pass = 0; pass < 3; pass++) {
        const int Ap = (pass == 2) ? 1 : 0;
        const int Bp = (pass == 1) ? 1 : 0;
#pragma unroll
        for (int ks = 0; ks < 4; ks++) {
            int kb = Bp * 64 + ks * 16 + (lane & 3) * 2;
#pragma unroll
            for (int nt = 0; nt < 16; nt++) {
                int n = nt * 8 + (lane >> 2);
                uint32_t b0 = *(const uint32_t*)(smBs + n * 272 + kb * 2);
                uint32_t b1 = *(const uint32_t*)(smBs + n * 272 + kb * 2 + 16);
                mma16816(d[nt], afr[Ap][ks], b0, b1);
            }
        }
    }

    {
        int r = wid * 16 + (lane >> 2);
        size_t row0 = (size_t)(b * NN + n0 + r) * NN + m0;
        size_t row8 = row0 + (size_t)8 * NN;
#pragma unroll
        for (int nt = 0; nt < 16; nt++) {
            int cj = nt * 8 + (lane & 3) * 2;
            float xm0 = xxm[cj], xm1 = xxm[cj + 1];
            float2 lo = make_float2(2.f * d[nt][0] - xm0, 2.f * d[nt][1] - xm1);
            float2 hi = make_float2(2.f * d[nt][2] - xm0, 2.f * d[nt][3] - xm1);
            *(float2*)&g_pd[row0 + cj] = lo;
            *(float2*)&g_pd[row8 + cj] = hi;
        }
    }
}

// ---------------- K2: top-20 per row — threshold-prefilter (exact) ----------------
// Warp per row. Pass 1: branchless lane max -> bitonic -> tau = 20th lane max
// (provably <= 20th-largest row value). Pass 2: ballot-compact values >= tau
// into smem buffer (expected ~40-80). Merge: 20 shfl-argmax rounds.
// Fallback (cnt > 256, ~impossible): exact predicated-insert scan.
__global__ __launch_bounds__(256) void k_topk() {
    __shared__ float bval[8][256];
    __shared__ int   bidx[8][256];
    int t = threadIdx.x, lane = t & 31, w = t >> 5;
    int g = blockIdx.x * 8 + w;
    const float* row = g_pd + (size_t)g * NN;

    // ---- pass 1: lane max (branchless, 4-way ILP) ----
    float m0 = -CUDART_INF_F, m1 = -CUDART_INF_F, m2 = -CUDART_INF_F, m3 = -CUDART_INF_F;
#pragma unroll 4
    for (int j = 0; j < 256; j += 4) {
        m0 = fmaxf(m0, row[j * 32 + lane]);
        m1 = fmaxf(m1, row[(j + 1) * 32 + lane]);
        m2 = fmaxf(m2, row[(j + 2) * 32 + lane]);
        m3 = fmaxf(m3, row[(j + 3) * 32 + lane]);
    }
    float m = fmaxf(fmaxf(m0, m1), fmaxf(m2, m3));

    // ---- bitonic sort of 32 lane maxima (descending), tau = 20th largest ----
#pragma unroll
    for (int k = 2; k <= 32; k <<= 1) {
#pragma unroll
        for (int jj = k >> 1; jj > 0; jj >>= 1) {
            float o = __shfl_xor_sync(0xffffffffu, m, jj);
            bool dirDesc = ((lane & k) == 0);
            bool lower   = ((lane & jj) == 0);
            float mx = fmaxf(m, o), mn = fminf(m, o);
            m = (dirDesc == lower) ? mx : mn;
        }
    }
    float tau = __shfl_sync(0xffffffffu, m, KK - 1);

    // ---- pass 2: ballot-compact candidates >= tau ----
    int base = 0;
#pragma unroll 1
    for (int j = 0; j < 256; j++) {
        float v = row[j * 32 + lane];
        bool p = (v >= tau);
        unsigned mask = __ballot_sync(0xffffffffu, p);
        if (mask) {
            int pos = base + __popc(mask & ((1u << lane) - 1));
            if (p && pos < 256) { bval[w][pos] = v; bidx[w][pos] = j * 32 + lane; }
            base += __popc(mask);
        }
    }
    __syncwarp();

    if (base <= 256) {
        // ---- merge: <=8 entries/lane, 20 rounds of shfl-argmax ----
        int cnt = base;
        float vv[8]; int ii[8];
#pragma unroll
        for (int r = 0; r < 8; r++) {
            int e = lane + r * 32;
            bool ok = (e < cnt);
            vv[r] = ok ? bval[w][e] : -CUDART_INF_F;
            ii[r] = ok ? bidx[w][e] : 0;
        }
        float lmax = -CUDART_INF_F; int lpos = 0, lidx = 0;
#pragma unroll
        for (int r = 0; r < 8; r++)
            if (vv[r] > lmax) { lmax = vv[r]; lpos = r; lidx = ii[r]; }

        for (int r = 0; r < KK; r++) {
            float v = lmax; int vi = lidx; int src = lane;
#pragma unroll
            for (int off = 16; off > 0; off >>= 1) {
                float ov = __shfl_xor_sync(0xffffffffu, v, off);
                int   oi = __shfl_xor_sync(0xffffffffu, vi, off);
                int   os = __shfl_xor_sync(0xffffffffu, src, off);
                if (ov > v || (ov == v && os < src)) { v = ov; vi = oi; src = os; }
            }
            if (lane == 0) g_idx[(size_t)g * KK + r] = vi;
            if (lane == src) {
#pragma unroll
                for (int q = 0; q < 8; q++)
                    if (q == lpos) vv[q] = -CUDART_INF_F;
                lmax = -CUDART_INF_F; lpos = 0; lidx = 0;
#pragma unroll
                for (int q = 0; q < 8; q++)
                    if (vv[q] > lmax) { lmax = vv[q]; lpos = q; lidx = ii[q]; }
            }
            __syncwarp();
        }
    } else {
        // ---- fallback (ties/pathological rows): exact insert scan ----
        float tv[KK]; int ti[KK];
#pragma unroll
        for (int q = 0; q < KK; q++) { tv[q] = -CUDART_INF_F; ti[q] = 0; }
        float thr = -CUDART_INF_F; int thrpos = 0;
#pragma unroll 1
        for (int j = 0; j < 256; j++) {
            float v = row[j * 32 + lane];
            if (v > thr) {
                int col = j * 32 + lane;
#pragma unroll
                for (int q = 0; q < KK; q++)
                    if (q == thrpos) { tv[q] = v; ti[q] = col; }
                thr = tv[0]; thrpos = 0;
#pragma unroll
                for (int q = 1; q < KK; q++)
                    if (tv[q] < thr) { thr = tv[q]; thrpos = q; }
            }
        }
        float lmax = -CUDART_INF_F; int lpos = 0;
#pragma unroll
        for (int q = 0; q < KK; q++)
            if (tv[q] > lmax) { lmax = tv[q]; lpos = q; }
        for (int r = 0; r < KK; r++) {
            float v = lmax; int src = lane;
#pragma unroll
            for (int off = 16; off > 0; off >>= 1) {
                float ov = __shfl_xor_sync(0xffffffffu, v, off);
                int   os = __shfl_xor_sync(0xffffffffu, src, off);
                if (ov > v || (ov == v && os < src)) { v = ov; src = os; }
            }
            if (lane == src) {
                int outi = 0;
#pragma unroll
                for (int q = 0; q < KK; q++)
                    if (q == lpos) outi = ti[q];
                g_idx[(size_t)g * KK + r] = outi;
#pragma unroll
                for (int q = 0; q < KK; q++)
                    if (q == lpos) tv[q] = -CUDART_INF_F;
                lmax = -CUDART_INF_F; lpos = 0;
#pragma unroll
                for (int q = 0; q < KK; q++)
                    if (tv[q] > lmax) { lmax = tv[q]; lpos = q; }
            }
            __syncwarp();
        }
    }
}

// ---------------- K3: P = W1a·x_n ; T = (W1b - W1a)·x_n  (ILP-4 accumulators) ----------------
__global__ __launch_bounds__(128) void k_pt(const float* __restrict__ W1) {
    extern __shared__ float sm[];
    float* Wt = sm;
    __shared__ float xr[64];
    int t = threadIdx.x;
    for (int s = t; s < 128 * 128; s += 128) {
        int d = s >> 7, c = s & 127;
        float wvv = W1[d * 128 + c];
        if (c >= 64) wvv -= W1[d * 128 + c - 64];
        Wt[c * 129 + d] = wvv;
    }
    __syncthreads();
    int g0 = blockIdx.x * 32;
    for (int nn = 0; nn < 32; nn++) {
        int g = g0 + nn;
        if (t < 64) xr[t] = g_xt[(size_t)g * CC + t];
        __syncthreads();
        float p0 = 0.f, p1 = 0.f, p2 = 0.f, p3 = 0.f;
        float t0 = 0.f, t1 = 0.f, t2 = 0.f, t3 = 0.f;
#pragma unroll
        for (int c = 0; c < 64; c += 4) {
            float x0 = xr[c], x1 = xr[c + 1], x2 = xr[c + 2], x3 = xr[c + 3];
            p0 = fmaf(Wt[c * 129 + t],       x0, p0);
            p1 = fmaf(Wt[(c + 1) * 129 + t], x1, p1);
            p2 = fmaf(Wt[(c + 2) * 129 + t], x2, p2);
            p3 = fmaf(Wt[(c + 3) * 129 + t], x3, p3);
            t0 = fmaf(Wt[(c + 64) * 129 + t], x0, t0);
            t1 = fmaf(Wt[(c + 65) * 129 + t], x1, t1);
            t2 = fmaf(Wt[(c + 66) * 129 + t], x2, t2);
            t3 = fmaf(Wt[(c + 67) * 129 + t], x3, t3);
        }
        g_pt[(size_t)g * 256 + t]       = (p0 + p1) + (p2 + p3);
        g_pt[(size_t)g * 256 + 128 + t] = (t0 + t1) + (t2 + t3);
        __syncthreads();
    }
}

// ---------------- K4: gather + softmax_k + g-collapse + W2 matvec (ILP-4) ----------------
__global__ __launch_bounds__(128) void k_out(const float* __restrict__ W2,
                                             float* __restrict__ out) {
    extern __shared__ float sm[];
    float* W2t = sm;
    __shared__ float gs[128];
    __shared__ float ctrs[64];
    __shared__ int   nid[KK];
    int t = threadIdx.x;
    for (int s = t; s < 128 * 128; s += 128) {
        int o = s >> 7, c = s & 127;
        W2t[c * 129 + o] = W2[o * 128 + c];
    }
    __syncthreads();
    int g0 = blockIdx.x * 16;
    for (int nn = 0; nn < 16; nn++) {
        int g = g0 + nn;
        int b = g >> 13, n = g & (NN - 1);
        if (t < KK) nid[t] = g_idx[(size_t)g * KK + t];
        if (t < 64) ctrs[t] = g_xt[(size_t)g * CC + t];
        float tvv = g_pt[(size_t)g * 256 + 128 + t];
        __syncthreads();

        float h[KK];
#pragma unroll
        for (int k = 0; k < KK; k++) {
            int ng = (b << 13) + nid[k];
            h[k] = g_pt[(size_t)ng * 256 + t] + tvv;
        }
        float hm = -CUDART_INF_F;
#pragma unroll
        for (int k = 0; k < KK; k++) hm = fmaxf(hm, h[k]);
        float s = 0.f;
#pragma unroll
        for (int k = 0; k < KK; k++) { float e = __expf(h[k] - hm); s += e; h[k] = e; }
        float inv = 1.f / s;

        float gd;
        if (t < 64) {
            float c0 = ctrs[t];
            float a0 = 0.f, a1 = 0.f, a2 = 0.f, a3 = 0.f;
#pragma unroll
            for (int k = 0; k < KK; k += 4) {
                a0 = fmaf(g_xt[(size_t)((b << 13) + nid[k])     * CC + t] - c0, h[k],     a0);
                a1 = fmaf(g_xt[(size_t)((b << 13) + nid[k + 1]) * CC + t] - c0, h[k + 1], a1);
                a2 = fmaf(g_xt[(size_t)((b << 13) + nid[k + 2]) * CC + t] - c0, h[k + 2], a2);
                a3 = fmaf(g_xt[(size_t)((b << 13) + nid[k + 3]) * CC + t] - c0, h[k + 3], a3);
            }
            gd = ((a0 + a1) + (a2 + a3)) * inv;
        } else {
            float s0 = 0.f, s1 = 0.f, s2 = 0.f, s3 = 0.f;
#pragma unroll
            for (int k = 0; k < KK; k += 4) {
                s0 += h[k]; s1 += h[k + 1]; s2 += h[k + 2]; s3 += h[k + 3];
            }
            gd = ctrs[t - 64] * ((s0 + s1) + (s2 + s3)) * inv;
        }
        gs[t] = gd;
        __syncthreads();

        float c0 = 0.f, c1 = 0.f, c2 = 0.f, c3 = 0.f;
#pragma unroll
        for (int c = 0; c < 128; c += 4) {
            c0 = fmaf(W2t[c * 129 + t],       gs[c],     c0);
            c1 = fmaf(W2t[(c + 1) * 129 + t], gs[c + 1], c1);
            c2 = fmaf(W2t[(c + 2) * 129 + t], gs[c + 2], c2);
            c3 = fmaf(W2t[(c + 3) * 129 + t], gs[c + 3], c3);
        }
        out[((size_t)b * OO + t) * NN + n] = (c0 + c1) + (c2 + c3);
        __syncthreads();
    }
}

// ---------------- launch ----------------
extern "C" void kernel_launch(void* const* d_in, const int* in_sizes, int n_in,
                              void* d_out, int out_size) {
    const float* x  = (const float*)d_in[0];
    const float* W1 = (const float*)d_in[1];
    const float* W2 = (const float*)d_in[2];
    float* out = (float*)d_out;

    cudaFuncSetAttribute(k_dist, cudaFuncAttributeMaxDynamicSharedMemorySize, SM_DIST);
    cudaFuncSetAttribute(k_pt,   cudaFuncAttributeMaxDynamicSharedMemorySize, 128 * 129 * 4);
    cudaFuncSetAttribute(k_out,  cudaFuncAttributeMaxDynamicSharedMemorySize, 128 * 129 * 4);

    k_split<<<BN / 256, 256>>>(x);
    k_nop<<<1, 32>>>(1);                 // k_topk lands in ncu's profiled 4th slot
    k_dist<<<dim3(64, 64, 4), 256, SM_DIST>>>();
    k_topk<<<BN / 8, 256>>>();
    k_pt<<<BN / 32, 128, 128 * 129 * 4>>>(W1);
    k_out<<<BN / 16, 128, 128 * 129 * 4>>>(W2, out);
}